// round 10
// baseline (speedup 1.0000x reference)
#include <cuda_runtime.h>
#include <cstdint>

#define N_NODES 100000
#define N_EDGES 1600000
#define NHID 64
#define NCLASS 40

typedef unsigned long long ull;

// Scratch (static device globals — no allocation)
__device__ float g_agg[N_NODES * NHID];
__device__ float g_h[N_NODES * NHID];

__device__ __forceinline__ uint32_t smem_u32(const void* p) {
    uint32_t a;
    asm("{ .reg .u64 t; cvta.to.shared.u64 t, %1; cvt.u32.u64 %0, t; }"
        : "=r"(a) : "l"(p));
    return a;
}

__device__ __forceinline__ void ffma2(ull& d, ull a, ull b) {
    asm("fma.rn.f32x2 %0, %1, %2, %0;" : "+l"(d) : "l"(a), "l"(b));
}
__device__ __forceinline__ ull pack2(float x) {
    ull r; asm("mov.b64 %0, {%1, %1};" : "=l"(r) : "f"(x)); return r;
}
__device__ __forceinline__ float2 unpack2(ull v) {
    float2 f; asm("mov.b64 {%0, %1}, %2;" : "=f"(f.x), "=f"(f.y) : "l"(v)); return f;
}

// ---------------------------------------------------------------------------
// float4 copy: agg := src  (self term "x +" of GIN layer 1)
// ---------------------------------------------------------------------------
__global__ void copy_kernel(float4* __restrict__ dst, const float4* __restrict__ src, int n4) {
    int i = blockIdx.x * blockDim.x + threadIdx.x;
    if (i < n4) dst[i] = src[i];
}

// ---------------------------------------------------------------------------
// Scatter-add via TMA bulk reduction:
//   agg[dst] += feat[src]  (256 B per edge)
// Each warp processes 8 edges/iteration: 32 lanes gather 64 B each (LDG.128 x4),
// stage into a 2 KB smem slot, fence to async proxy, then lanes 0..7 each issue
// one cp.reduce.async.bulk (256 B f32 add) to global. Double-buffered smem
// slots recycled via cp.async.bulk.wait_group.read. This removes the 16
// RED lanes/edge from the LSU (prev. binder at ~1.29 cyc/lane) and moves the
// RMW onto the TMA/L2 path.
// ---------------------------------------------------------------------------
__global__ __launch_bounds__(256) void scatter_tma(
    const float* __restrict__ feat,
    float* __restrict__ agg,
    const void* __restrict__ ei_raw)
{
    __shared__ __align__(128) float4 buf[8][2][128];  // warp, slot, 2KB each
    int t = threadIdx.x;
    int w = t >> 5, lane = t & 31;

    // dtype detect: int64 vs int32 (x64-disabled JAX). If really int32, the
    // high word of a packed pair is a (almost surely nonzero) node index.
    const long long* ei64 = (const long long*)ei_raw;
    long long p0 = ei64[0], p1 = ei64[1], p2 = ei64[2];
    bool is64 = ((unsigned long long)p0 < (1ULL << 32)) &&
                ((unsigned long long)p1 < (1ULL << 32)) &&
                ((unsigned long long)p2 < (1ULL << 32));
    const int* ei32 = (const int*)ei_raw;

    int gw = blockIdx.x * 8 + w;
    int stride = gridDim.x * 8 * 8;   // edges covered per sweep
    int slot = 0;
    uint32_t sbase = smem_u32(&buf[w][0][0]);

    for (int base = gw * 8; base < N_EDGES; base += stride) {
        // recycle slot: op that read it was committed 2 iterations ago
        asm volatile("cp.async.bulk.wait_group.read 1;" ::: "memory");

        int e = base + (lane >> 2);
        int seg = lane & 3;
        bool ok = e < N_EDGES;
        int s = 0;
        if (ok) s = is64 ? (int)ei64[e] : ei32[e];
        const float4* gp = (const float4*)(feat + (size_t)s * NHID) + seg * 4;
        float4 v0, v1, v2, v3;
        if (ok) { v0 = gp[0]; v1 = gp[1]; v2 = gp[2]; v3 = gp[3]; }
        else    { v0 = v1 = v2 = v3 = make_float4(0.f, 0.f, 0.f, 0.f); }

        float4* bp = &buf[w][slot][lane * 4];
        bp[0] = v0; bp[1] = v1; bp[2] = v2; bp[3] = v3;

        __syncwarp();
        asm volatile("fence.proxy.async.shared::cta;" ::: "memory");

        if (lane < 8) {
            int e2 = base + lane;
            if (e2 < N_EDGES) {
                int d = is64 ? (int)ei64[N_EDGES + e2] : ei32[N_EDGES + e2];
                float* gdst = agg + (size_t)d * NHID;
                uint32_t sa = sbase + (uint32_t)slot * 2048 + (uint32_t)lane * 256;
                asm volatile(
                    "cp.reduce.async.bulk.global.shared::cta.bulk_group.add.f32 [%0], [%1], 256;"
                    :: "l"(gdst), "r"(sa) : "memory");
            }
        }
        asm volatile("cp.async.bulk.commit_group;" ::: "memory");
        slot ^= 1;
    }
    asm volatile("cp.async.bulk.wait_group 0;" ::: "memory");
}

// ---------------------------------------------------------------------------
// out = relu(A @ W + b)  [+ optional dual store to out2, possibly == A]
// FFMA2 (fma.rn.f32x2): 4 rows x 16 cols per thread as 8 packed f32x2 accums.
// W pairs come straight from smem as ulonglong2 (LDS.128), bias folded into
// accumulator init. __syncthreads before the epilogue makes out2==A safe.
// ---------------------------------------------------------------------------
__global__ __launch_bounds__(256) void gemm_relu_kernel(
    const float* __restrict__ A, const float* __restrict__ W,
    const float* __restrict__ b, float* __restrict__ out,
    float* __restrict__ out2, int nrows)
{
    __shared__ __align__(16) float Ws[64 * 64];
    __shared__ __align__(16) float bs[64];
    int t = threadIdx.x;

    const float4* Wg = (const float4*)W;
    float4* Wsv = (float4*)Ws;
    #pragma unroll
    for (int i = 0; i < 4; i++) Wsv[t + i * 256] = Wg[t + i * 256];
    if (t < 64) bs[t] = b[t];
    __syncthreads();

    int cg = t >> 6;          // column group: cols [cg*16, cg*16+16)
    int rq = t & 63;
    int r0 = blockIdx.x * 256 + rq * 4;

    ull acc[4][8];
    const ull* bs2 = (const ull*)bs;
    #pragma unroll
    for (int rr = 0; rr < 4; rr++)
        #pragma unroll
        for (int j = 0; j < 8; j++) acc[rr][j] = bs2[cg * 8 + j];

    for (int k = 0; k < 64; k += 4) {
        float xv[4][4];
        #pragma unroll
        for (int rr = 0; rr < 4; rr++) {
            int r = r0 + rr;
            float4 v = (r < nrows)
                ? *reinterpret_cast<const float4*>(A + (size_t)r * 64 + k)
                : make_float4(0.f, 0.f, 0.f, 0.f);
            xv[rr][0] = v.x; xv[rr][1] = v.y; xv[rr][2] = v.z; xv[rr][3] = v.w;
        }
        #pragma unroll
        for (int kk = 0; kk < 4; kk++) {
            const ulonglong2* wr =
                reinterpret_cast<const ulonglong2*>(Ws + (k + kk) * 64 + cg * 16);
            ull w2[8];
            #pragma unroll
            for (int j = 0; j < 4; j++) {
                ulonglong2 ww = wr[j];
                w2[j * 2 + 0] = ww.x; w2[j * 2 + 1] = ww.y;
            }
            #pragma unroll
            for (int rr = 0; rr < 4; rr++) {
                ull a2 = pack2(xv[rr][kk]);
                #pragma unroll
                for (int j = 0; j < 8; j++) ffma2(acc[rr][j], a2, w2[j]);
            }
        }
    }

    __syncthreads();  // all reads of A done before possible in-place store (out2==A)

    #pragma unroll
    for (int rr = 0; rr < 4; rr++) {
        int r = r0 + rr;
        if (r < nrows) {
            #pragma unroll
            for (int j = 0; j < 4; j++) {
                float2 lo = unpack2(acc[rr][j * 2 + 0]);
                float2 hi = unpack2(acc[rr][j * 2 + 1]);
                float4 o;
                o.x = fmaxf(lo.x, 0.f); o.y = fmaxf(lo.y, 0.f);
                o.z = fmaxf(hi.x, 0.f); o.w = fmaxf(hi.y, 0.f);
                size_t off = (size_t)r * 64 + cg * 16 + j * 4;
                *reinterpret_cast<float4*>(out + off) = o;
                if (out2) *reinterpret_cast<float4*>(out2 + off) = o;
            }
        }
    }
}

// ---------------------------------------------------------------------------
// out = log_softmax(A @ Wf + bf); FFMA2, 2 rows/thread, logits in registers.
// ---------------------------------------------------------------------------
__global__ __launch_bounds__(256) void final_kernel(
    const float* __restrict__ A, const float* __restrict__ W,
    const float* __restrict__ b, float* __restrict__ out, int nrows)
{
    __shared__ __align__(16) float Ws[64 * NCLASS];
    __shared__ __align__(16) float bs[NCLASS];
    int t = threadIdx.x;
    for (int i = t; i < 64 * NCLASS / 4; i += 256)
        ((float4*)Ws)[i] = ((const float4*)W)[i];
    if (t < NCLASS) bs[t] = b[t];
    __syncthreads();

    int r0 = (blockIdx.x * 256 + t) * 2;

    ull acc[2][NCLASS / 2];
    const ull* bs2 = (const ull*)bs;
    #pragma unroll
    for (int rr = 0; rr < 2; rr++)
        #pragma unroll
        for (int c = 0; c < NCLASS / 2; c++) acc[rr][c] = bs2[c];

    for (int k = 0; k < 64; k += 4) {
        float xv[2][4];
        #pragma unroll
        for (int rr = 0; rr < 2; rr++) {
            int r = r0 + rr;
            float4 v = (r < nrows)
                ? *reinterpret_cast<const float4*>(A + (size_t)r * 64 + k)
                : make_float4(0.f, 0.f, 0.f, 0.f);
            xv[rr][0] = v.x; xv[rr][1] = v.y; xv[rr][2] = v.z; xv[rr][3] = v.w;
        }
        #pragma unroll
        for (int kk = 0; kk < 4; kk++) {
            const ulonglong2* wr =
                reinterpret_cast<const ulonglong2*>(Ws + (k + kk) * NCLASS);
            ull a0 = pack2(xv[0][kk]);
            ull a1 = pack2(xv[1][kk]);
            #pragma unroll
            for (int j = 0; j < NCLASS / 4; j++) {
                ulonglong2 ww = wr[j];
                ffma2(acc[0][j * 2 + 0], a0, ww.x);
                ffma2(acc[0][j * 2 + 1], a0, ww.y);
                ffma2(acc[1][j * 2 + 0], a1, ww.x);
                ffma2(acc[1][j * 2 + 1], a1, ww.y);
            }
        }
    }

    #pragma unroll
    for (int rr = 0; rr < 2; rr++) {
        int r = r0 + rr;
        if (r >= nrows) continue;
        float lg[NCLASS];
        #pragma unroll
        for (int c = 0; c < NCLASS / 2; c++) {
            float2 f = unpack2(acc[rr][c]);
            lg[c * 2 + 0] = f.x; lg[c * 2 + 1] = f.y;
        }
        float m = lg[0];
        #pragma unroll
        for (int c = 1; c < NCLASS; c++) m = fmaxf(m, lg[c]);
        float s = 0.f;
        #pragma unroll
        for (int c = 0; c < NCLASS; c++) s += __expf(lg[c] - m);
        float lse = m + __logf(s);
        float* op = out + (size_t)r * NCLASS;
        #pragma unroll
        for (int c4 = 0; c4 < NCLASS / 4; c4++) {
            float4 o;
            o.x = lg[c4 * 4 + 0] - lse;
            o.y = lg[c4 * 4 + 1] - lse;
            o.z = lg[c4 * 4 + 2] - lse;
            o.w = lg[c4 * 4 + 3] - lse;
            *reinterpret_cast<float4*>(op + c4 * 4) = o;
        }
    }
}

// ---------------------------------------------------------------------------
extern "C" void kernel_launch(void* const* d_in, const int* in_sizes, int n_in,
                              void* d_out, int out_size) {
    const float* x  = (const float*)d_in[0];
    const void*  ei = d_in[1];
    const float* W1 = (const float*)d_in[2];
    const float* b1 = (const float*)d_in[3];
    const float* W2 = (const float*)d_in[4];
    const float* b2 = (const float*)d_in[5];
    const float* Wf = (const float*)d_in[6];
    const float* bf = (const float*)d_in[7];
    float* out = (float*)d_out;

    float *agg, *h;
    cudaGetSymbolAddress((void**)&agg, g_agg);
    cudaGetSymbolAddress((void**)&h, g_h);

    const int n4 = N_NODES * NHID / 4;
    const int copy_blocks = (n4 + 255) / 256;
    const int scat_blocks = 888;                 // 6 CTAs/SM, 8 warps each
    const int gemm_blocks = (N_NODES + 255) / 256;
    const int fin_blocks  = (N_NODES + 511) / 512;

    // Layer 1: agg = x + sum_{j->i} x_j ; h = relu(agg @ W1 + b1); agg := h (fused)
    copy_kernel<<<copy_blocks, 256>>>((float4*)agg, (const float4*)x, n4);
    scatter_tma<<<scat_blocks, 256>>>(x, agg, ei);
    gemm_relu_kernel<<<gemm_blocks, 256>>>(agg, W1, b1, h, agg, N_NODES);

    // Layer 2: agg already holds h (self term); add neighbor sums, then GEMM
    scatter_tma<<<scat_blocks, 256>>>(h, agg, ei);
    gemm_relu_kernel<<<gemm_blocks, 256>>>(agg, W2, b2, h, nullptr, N_NODES);

    // Classifier + fused log_softmax
    final_kernel<<<fin_blocks, 256>>>(h, Wf, bf, out, N_NODES);
}

// round 11
// speedup vs baseline: 1.6137x; 1.6137x over previous
#include <cuda_runtime.h>
#include <cstdint>

#define N_NODES 100000
#define N_EDGES 1600000
#define NHID 64
#define NCLASS 40
#define SCAN_B 512
#define NBLK ((N_NODES + SCAN_B - 1) / SCAN_B)   // 196

// Scratch (static device globals — no allocation)
__device__ float g_agg[N_NODES * NHID];
__device__ float g_h[N_NODES * NHID];
__device__ int   g_deg[N_NODES];
__device__ int   g_off[N_NODES];
__device__ int   g_cur[N_NODES];
__device__ int   g_adj[N_EDGES];
__device__ int   g_bsum[NBLK];

// ---------------------------------------------------------------------------
// Edge-index dtype detection (int64 vs x64-disabled int32): if really int32,
// the high half of a packed "int64" word is a (almost surely nonzero) index.
// ---------------------------------------------------------------------------
__device__ __forceinline__ bool ei_is64(const void* ei_raw) {
    const long long* e = (const long long*)ei_raw;
    return ((unsigned long long)e[0] < (1ULL << 32)) &&
           ((unsigned long long)e[1] < (1ULL << 32)) &&
           ((unsigned long long)e[2] < (1ULL << 32));
}
__device__ __forceinline__ int ei_at(const void* ei_raw, bool is64, int i) {
    return is64 ? (int)((const long long*)ei_raw)[i]
                : ((const int*)ei_raw)[i];
}

// ---------------------------------------------------------------------------
// CSR construction
// ---------------------------------------------------------------------------
__global__ void zero_deg_kernel(int* __restrict__ deg) {
    int i = blockIdx.x * blockDim.x + threadIdx.x;
    if (i < N_NODES) deg[i] = 0;
}

__global__ void hist_kernel(const void* __restrict__ ei, int* __restrict__ deg) {
    int e = blockIdx.x * blockDim.x + threadIdx.x;
    if (e >= N_EDGES) return;
    bool is64 = ei_is64(ei);
    int d = ei_at(ei, is64, N_EDGES + e);
    atomicAdd(&deg[d], 1);
}

// scan phase A: per-block sums of 512 deg entries
__global__ __launch_bounds__(SCAN_B) void scanA_kernel(
    const int* __restrict__ deg, int* __restrict__ bsum)
{
    __shared__ int s[SCAN_B];
    int t = threadIdx.x;
    int i = blockIdx.x * SCAN_B + t;
    s[t] = (i < N_NODES) ? deg[i] : 0;
    __syncthreads();
    #pragma unroll
    for (int k = SCAN_B / 2; k > 0; k >>= 1) {
        if (t < k) s[t] += s[t + k];
        __syncthreads();
    }
    if (t == 0) bsum[blockIdx.x] = s[0];
}

// scan phase B: exclusive scan of NBLK block sums (serial in smem, tiny)
__global__ __launch_bounds__(256) void scanB_kernel(int* __restrict__ bsum) {
    __shared__ int s[NBLK];
    int t = threadIdx.x;
    if (t < NBLK) s[t] = bsum[t];
    __syncthreads();
    if (t == 0) {
        int run = 0;
        for (int i = 0; i < NBLK; i++) { int v = s[i]; s[i] = run; run += v; }
    }
    __syncthreads();
    if (t < NBLK) bsum[t] = s[t];
}

// scan phase C: per-block exclusive scan + carry -> off, cur
__global__ __launch_bounds__(SCAN_B) void scanC_kernel(
    const int* __restrict__ deg, const int* __restrict__ bsum,
    int* __restrict__ off, int* __restrict__ cur)
{
    __shared__ int sa[SCAN_B], sb[SCAN_B];
    int t = threadIdx.x;
    int i = blockIdx.x * SCAN_B + t;
    int v = (i < N_NODES) ? deg[i] : 0;
    sa[t] = v;
    __syncthreads();
    int* src = sa; int* dst = sb;
    #pragma unroll
    for (int k = 1; k < SCAN_B; k <<= 1) {      // Hillis-Steele inclusive
        dst[t] = (t >= k) ? src[t] + src[t - k] : src[t];
        __syncthreads();
        int* tmp = src; src = dst; dst = tmp;
    }
    if (i < N_NODES) {
        int excl = bsum[blockIdx.x] + src[t] - v;
        off[i] = excl;
        cur[i] = excl;
    }
}

__global__ void fill_kernel(const void* __restrict__ ei,
                            int* __restrict__ cur, int* __restrict__ adj) {
    int e = blockIdx.x * blockDim.x + threadIdx.x;
    if (e >= N_EDGES) return;
    bool is64 = ei_is64(ei);
    int s = ei_at(ei, is64, e);
    int d = ei_at(ei, is64, N_EDGES + e);
    int pos = atomicAdd(&cur[d], 1);
    adj[pos] = s;
}

// ---------------------------------------------------------------------------
// Pull aggregation: agg[i] = feat[i] + sum_{j in adj[off[i]:off[i]+deg[i]]} feat[j]
// 16 threads per node (one float4 each). Depth-2 index prefetch breaks the
// idx->feat dependent-load chain (MLP=2 per thread); adj reads by the 16-lane
// group hit the same address -> single coalesced broadcast request.
// ---------------------------------------------------------------------------
__global__ __launch_bounds__(256) void aggregate_kernel(
    const float* __restrict__ feat, float* __restrict__ aggout,
    const int* __restrict__ off, const int* __restrict__ deg,
    const int* __restrict__ adj)
{
    int tid = blockIdx.x * blockDim.x + threadIdx.x;
    int node = tid >> 4;
    if (node >= N_NODES) return;
    int q = tid & 15;

    int o = off[node];
    int d = deg[node];

    float4 acc = ((const float4*)(feat + (size_t)node * NHID))[q];   // self term

    int i0 = (d > 0) ? __ldg(adj + o) : 0;
    int i1 = (d > 1) ? __ldg(adj + o + 1) : 0;
    for (int j = 0; j < d; j++) {
        int inext = (j + 2 < d) ? __ldg(adj + o + j + 2) : 0;
        float4 v = ((const float4*)(feat + (size_t)i0 * NHID))[q];
        acc.x += v.x; acc.y += v.y; acc.z += v.z; acc.w += v.w;
        i0 = i1; i1 = inext;
    }
    ((float4*)(aggout + (size_t)node * NHID))[q] = acc;
}

// ---------------------------------------------------------------------------
// out = relu(A @ W + b)   (round-9 scalar-FFMA version — known good)
// ---------------------------------------------------------------------------
__global__ __launch_bounds__(256) void gemm_relu_kernel(
    const float* __restrict__ A, const float* __restrict__ W,
    const float* __restrict__ b, float* __restrict__ out, int nrows)
{
    __shared__ __align__(16) float Ws[64 * 64];
    __shared__ float bs[64];
    int t = threadIdx.x;

    const float4* Wg = (const float4*)W;
    float4* Wsv = (float4*)Ws;
    #pragma unroll
    for (int i = 0; i < 4; i++) Wsv[t + i * 256] = Wg[t + i * 256];
    if (t < 64) bs[t] = b[t];
    __syncthreads();

    int cg = t >> 6;
    int rq = t & 63;
    int r0 = blockIdx.x * 256 + rq * 4;

    float acc[4][16];
    #pragma unroll
    for (int rr = 0; rr < 4; rr++)
        #pragma unroll
        for (int c = 0; c < 16; c++) acc[rr][c] = 0.f;

    for (int k = 0; k < 64; k += 4) {
        float xv[4][4];
        #pragma unroll
        for (int rr = 0; rr < 4; rr++) {
            int r = r0 + rr;
            float4 v = (r < nrows)
                ? *reinterpret_cast<const float4*>(A + (size_t)r * 64 + k)
                : make_float4(0.f, 0.f, 0.f, 0.f);
            xv[rr][0] = v.x; xv[rr][1] = v.y; xv[rr][2] = v.z; xv[rr][3] = v.w;
        }
        #pragma unroll
        for (int kk = 0; kk < 4; kk++) {
            const float4* wr = reinterpret_cast<const float4*>(Ws + (k + kk) * 64 + cg * 16);
            float w[16];
            #pragma unroll
            for (int j = 0; j < 4; j++) {
                float4 ww = wr[j];
                w[j*4+0] = ww.x; w[j*4+1] = ww.y; w[j*4+2] = ww.z; w[j*4+3] = ww.w;
            }
            #pragma unroll
            for (int rr = 0; rr < 4; rr++) {
                float a = xv[rr][kk];
                #pragma unroll
                for (int c = 0; c < 16; c++) acc[rr][c] += a * w[c];
            }
        }
    }

    #pragma unroll
    for (int rr = 0; rr < 4; rr++) {
        int r = r0 + rr;
        if (r < nrows) {
            float* op = out + (size_t)r * 64 + cg * 16;
            #pragma unroll
            for (int j = 0; j < 4; j++) {
                float4 o;
                o.x = fmaxf(acc[rr][j*4+0] + bs[cg*16 + j*4+0], 0.f);
                o.y = fmaxf(acc[rr][j*4+1] + bs[cg*16 + j*4+1], 0.f);
                o.z = fmaxf(acc[rr][j*4+2] + bs[cg*16 + j*4+2], 0.f);
                o.w = fmaxf(acc[rr][j*4+3] + bs[cg*16 + j*4+3], 0.f);
                *reinterpret_cast<float4*>(op + j * 4) = o;
            }
        }
    }
}

// ---------------------------------------------------------------------------
// out = log_softmax(A @ Wf + bf)   (round-9 version)
// ---------------------------------------------------------------------------
__global__ __launch_bounds__(256) void final_kernel(
    const float* __restrict__ A, const float* __restrict__ W,
    const float* __restrict__ b, float* __restrict__ out, int nrows)
{
    __shared__ __align__(16) float Ws[64 * NCLASS];
    __shared__ float bs[NCLASS];
    int t = threadIdx.x;
    for (int i = t; i < 64 * NCLASS / 4; i += 256)
        ((float4*)Ws)[i] = ((const float4*)W)[i];
    if (t < NCLASS) bs[t] = b[t];
    __syncthreads();

    int r0 = (blockIdx.x * 256 + t) * 2;

    float acc[2][NCLASS];
    #pragma unroll
    for (int rr = 0; rr < 2; rr++)
        #pragma unroll
        for (int c = 0; c < NCLASS; c++) acc[rr][c] = bs[c];

    for (int k = 0; k < 64; k += 4) {
        float xv[2][4];
        #pragma unroll
        for (int rr = 0; rr < 2; rr++) {
            int r = r0 + rr;
            float4 v = (r < nrows)
                ? *reinterpret_cast<const float4*>(A + (size_t)r * 64 + k)
                : make_float4(0.f, 0.f, 0.f, 0.f);
            xv[rr][0] = v.x; xv[rr][1] = v.y; xv[rr][2] = v.z; xv[rr][3] = v.w;
        }
        #pragma unroll
        for (int kk = 0; kk < 4; kk++) {
            const float4* wr = reinterpret_cast<const float4*>(Ws + (k + kk) * NCLASS);
            #pragma unroll
            for (int c4 = 0; c4 < NCLASS / 4; c4++) {
                float4 ww = wr[c4];
                #pragma unroll
                for (int rr = 0; rr < 2; rr++) {
                    float a = xv[rr][kk];
                    acc[rr][c4*4+0] += a * ww.x;
                    acc[rr][c4*4+1] += a * ww.y;
                    acc[rr][c4*4+2] += a * ww.z;
                    acc[rr][c4*4+3] += a * ww.w;
                }
            }
        }
    }

    #pragma unroll
    for (int rr = 0; rr < 2; rr++) {
        int r = r0 + rr;
        if (r >= nrows) continue;
        float m = acc[rr][0];
        #pragma unroll
        for (int c = 1; c < NCLASS; c++) m = fmaxf(m, acc[rr][c]);
        float s = 0.f;
        #pragma unroll
        for (int c = 0; c < NCLASS; c++) s += __expf(acc[rr][c] - m);
        float lse = m + __logf(s);
        float* op = out + (size_t)r * NCLASS;
        #pragma unroll
        for (int c4 = 0; c4 < NCLASS / 4; c4++) {
            float4 o;
            o.x = acc[rr][c4*4+0] - lse;
            o.y = acc[rr][c4*4+1] - lse;
            o.z = acc[rr][c4*4+2] - lse;
            o.w = acc[rr][c4*4+3] - lse;
            *reinterpret_cast<float4*>(op + c4 * 4) = o;
        }
    }
}

// ---------------------------------------------------------------------------
extern "C" void kernel_launch(void* const* d_in, const int* in_sizes, int n_in,
                              void* d_out, int out_size) {
    const float* x  = (const float*)d_in[0];
    const void*  ei = d_in[1];
    const float* W1 = (const float*)d_in[2];
    const float* b1 = (const float*)d_in[3];
    const float* W2 = (const float*)d_in[4];
    const float* b2 = (const float*)d_in[5];
    const float* Wf = (const float*)d_in[6];
    const float* bf = (const float*)d_in[7];
    float* out = (float*)d_out;

    float *agg, *h;
    int *deg, *off, *cur, *adj, *bsum;
    cudaGetSymbolAddress((void**)&agg,  g_agg);
    cudaGetSymbolAddress((void**)&h,    g_h);
    cudaGetSymbolAddress((void**)&deg,  g_deg);
    cudaGetSymbolAddress((void**)&off,  g_off);
    cudaGetSymbolAddress((void**)&cur,  g_cur);
    cudaGetSymbolAddress((void**)&adj,  g_adj);
    cudaGetSymbolAddress((void**)&bsum, g_bsum);

    const int edge_blocks = (N_EDGES + 255) / 256;
    const int node_blocks = (N_NODES + 255) / 256;
    const int agg_blocks  = (N_NODES * 16 + 255) / 256;
    const int gemm_blocks = (N_NODES + 255) / 256;
    const int fin_blocks  = (N_NODES + 511) / 512;

    // ---- CSR build (once per call, reused by both layers) ----
    zero_deg_kernel<<<node_blocks, 256>>>(deg);
    hist_kernel<<<edge_blocks, 256>>>(ei, deg);
    scanA_kernel<<<NBLK, SCAN_B>>>(deg, bsum);
    scanB_kernel<<<1, 256>>>(bsum);
    scanC_kernel<<<NBLK, SCAN_B>>>(deg, bsum, off, cur);
    fill_kernel<<<edge_blocks, 256>>>(ei, cur, adj);

    // ---- Layer 1: agg = x + sum_nbr x ; h = relu(agg @ W1 + b1) ----
    aggregate_kernel<<<agg_blocks, 256>>>(x, agg, off, deg, adj);
    gemm_relu_kernel<<<gemm_blocks, 256>>>(agg, W1, b1, h, N_NODES);

    // ---- Layer 2 ----
    aggregate_kernel<<<agg_blocks, 256>>>(h, agg, off, deg, adj);
    gemm_relu_kernel<<<gemm_blocks, 256>>>(agg, W2, b2, h, N_NODES);

    // ---- Classifier + fused log_softmax ----
    final_kernel<<<fin_blocks, 256>>>(h, Wf, bf, out, N_NODES);
}